// round 15
// baseline (speedup 1.0000x reference)
#include <cuda_runtime.h>
#include <cuda_fp16.h>
#include <math.h>
#include <stdint.h>

#define EMBED 384
#define HEADS 6
#define HS    64
#define BATCH 64
#define SEQ   256
#define ROWS  (BATCH*SEQ)     // 16384
#define NQKV  (3*EMBED)       // 1152
#define KW    (EMBED/2)       // 192 k-words (half2)

// ------------------------- device scratch (no allocs allowed) ----------------
__device__ float    g_qkv   [ROWS*NQKV];
__device__ float    g_attn  [ROWS*EMBED];
__device__ float    g_ff    [ROWS*EMBED];
__device__ uint32_t g_wqkv16[KW*NQKV];    // half2 words, [k_word][n]
__device__ uint32_t g_wp16  [KW*EMBED];
__device__ uint32_t g_w116  [KW*EMBED];
__device__ uint32_t g_w216  [KW*EMBED];
__device__ float    g_bqkv  [NQKV];
__device__ float2   g_stats [ROWS];

// ------------------------- helpers ------------------------------------------
__device__ __forceinline__ uint32_t f2tf32(float x) {
    uint32_t r;
    asm("cvt.rna.tf32.f32 %0, %1;" : "=r"(r) : "f"(x));
    return r;
}

__device__ __forceinline__ uint32_t pack_half2(float a, float b) {
    __half2 h = __floats2half2_rn(a, b);
    return *reinterpret_cast<uint32_t*>(&h);
}

__device__ __forceinline__ void mma_tf32(float d[4], const uint32_t a[4],
                                         const uint32_t b[2]) {
    asm volatile(
        "mma.sync.aligned.m16n8k8.row.col.f32.tf32.tf32.f32 "
        "{%0,%1,%2,%3}, {%4,%5,%6,%7}, {%8,%9}, {%0,%1,%2,%3};\n"
        : "+f"(d[0]), "+f"(d[1]), "+f"(d[2]), "+f"(d[3])
        : "r"(a[0]), "r"(a[1]), "r"(a[2]), "r"(a[3]), "r"(b[0]), "r"(b[1]));
}

__device__ __forceinline__ void mma_f16(float d[4], const uint32_t a[4],
                                        const uint32_t b[2]) {
    asm volatile(
        "mma.sync.aligned.m16n8k16.row.col.f32.f16.f16.f32 "
        "{%0,%1,%2,%3}, {%4,%5,%6,%7}, {%8,%9}, {%0,%1,%2,%3};\n"
        : "+f"(d[0]), "+f"(d[1]), "+f"(d[2]), "+f"(d[3])
        : "r"(a[0]), "r"(a[1]), "r"(a[2]), "r"(a[3]), "r"(b[0]), "r"(b[1]));
}

__device__ __forceinline__ void cp_async16(uint32_t saddr, const void* g) {
    asm volatile("cp.async.cg.shared.global [%0], [%1], 16;"
                 :: "r"(saddr), "l"(g));
}
#define CP_COMMIT() asm volatile("cp.async.commit_group;")
#define CP_WAIT0()  asm volatile("cp.async.wait_group 0;")

__device__ __forceinline__ uint32_t smem_u32(const void* p) {
    return (uint32_t)__cvta_generic_to_shared(p);
}

// ------------------------- weight packing (half2 word layout) ---------------
__global__ void pack_qkv16_kernel(const float* __restrict__ Wq,
                                  const float* __restrict__ Wk,
                                  const float* __restrict__ Wv,
                                  const float* __restrict__ bq,
                                  const float* __restrict__ bk,
                                  const float* __restrict__ bv,
                                  uint32_t* __restrict__ Wt,
                                  float* __restrict__ bout) {
    int idx = blockIdx.x * 256 + threadIdx.x;
    if (idx < KW * NQKV) {
        int w   = idx / NQKV;        // k-word (c pair)
        int n   = idx % NQKV;
        int sel = n / EMBED;
        int hd  = n % EMBED;
        int h   = hd / HS;
        int d   = hd % HS;
        const float* W = (sel == 0) ? Wq : (sel == 1) ? Wk : Wv;
        float v0 = W[((size_t)h * EMBED + 2 * w)     * HS + d];
        float v1 = W[((size_t)h * EMBED + 2 * w + 1) * HS + d];
        Wt[idx] = pack_half2(v0, v1);
    }
    if (idx < NQKV) {
        int sel = idx / EMBED;
        int hd  = idx % EMBED;
        const float* bb = (sel == 0) ? bq : (sel == 1) ? bk : bv;
        bout[idx] = bb[hd];
    }
}

__global__ void pack_w16_kernel(const float* __restrict__ W,
                                uint32_t* __restrict__ Wt) {
    int idx = blockIdx.x * 256 + threadIdx.x;
    if (idx < KW * EMBED) {
        int w = idx / EMBED;
        int n = idx % EMBED;
        Wt[idx] = pack_half2(W[(size_t)(2 * w) * EMBED + n],
                             W[(size_t)(2 * w + 1) * EMBED + n]);
    }
}

// ------------------------- LN stats ------------------------------------------
__global__ __launch_bounds__(256)
void ln_stats_kernel(const float* __restrict__ x, float2* __restrict__ st) {
    int row  = blockIdx.x * 8 + (threadIdx.x >> 5);
    int lane = threadIdx.x & 31;
    const float4* xr = reinterpret_cast<const float4*>(x + (size_t)row * EMBED);
    float s = 0.f, s2 = 0.f;
    #pragma unroll
    for (int i = 0; i < 3; i++) {
        float4 v = xr[lane + 32 * i];
        s  += v.x + v.y + v.z + v.w;
        s2 += v.x * v.x + v.y * v.y + v.z * v.z + v.w * v.w;
    }
    #pragma unroll
    for (int o = 16; o; o >>= 1) {
        s  += __shfl_xor_sync(0xffffffffu, s,  o);
        s2 += __shfl_xor_sync(0xffffffffu, s2, o);
    }
    if (lane == 0) {
        float mu  = s * (1.0f / EMBED);
        float var = s2 * (1.0f / EMBED) - mu * mu;
        st[row] = make_float2(mu, rsqrtf(var + 1e-5f));
    }
}

// ------------------------- FP16 tensor-core GEMM ----------------------------
// C[M,N] = A'[M,384] @ B[384,N] (+bias, opt relu, opt residual)
// A' = LN ? layernorm(A) : A (f32 in gmem, converted RN to half on STS).
// B pre-packed half2 words [k_word][n].  CTA 128x128, k-tile 64 (=32 words),
// 6 k-tiles, double-buffered, one sync per tile. mma m16n8k16 f16, f32 accum.
#define A_PITCH 36     // words; frag addr mod 32 = 4*gid + tig -> conflict-free
#define B_PITCH 136    // words; 136 mod 32 = 8 -> 8*tig + gid -> conflict-free
#define AS_WORDS (128 * A_PITCH)                 // 4608
#define BS_WORDS (32 * B_PITCH)                  // 4352
#define STG_WORDS (AS_WORDS + BS_WORDS)          // 8960
#define SM_GEMM_BYTES (2 * STG_WORDS * 4)        // 71680

template<bool LN, bool RELU>
__global__ __launch_bounds__(256)
void gemm_f16(const float* __restrict__ A, const uint32_t* __restrict__ Bw,
              const float* __restrict__ bias, const float* __restrict__ res,
              float* __restrict__ C, int N,
              const float2* __restrict__ stats,
              const float* __restrict__ lng, const float* __restrict__ lnb) {
    extern __shared__ uint32_t gsh[];
    const uint32_t smb = smem_u32(gsh);

    const int tid  = threadIdx.x;
    const int bm   = blockIdx.y * 128;
    const int bn   = blockIdx.x * 128;
    const int warp = tid >> 5;
    const int lane = tid & 31;
    const int wm   = (warp >> 2) * 64;
    const int wn   = (warp & 3) * 32;
    const int gid  = lane >> 2;
    const int tig  = lane & 3;

    float acc[4][4][4];
    #pragma unroll
    for (int i = 0; i < 4; i++)
        #pragma unroll
        for (int j = 0; j < 4; j++)
            #pragma unroll
            for (int r = 0; r < 4; r++) acc[i][j][r] = 0.f;

    // A staging: 8 chunks of float4 -> 2 half2 words each
    uint2 aS[8];
    const int a_row = tid >> 4;          // 0..15 (+16*it)
    const int a_f4  = tid & 15;          // float4 index within 64-float row

    auto ldgA = [&](int kt) {
        const int k0 = kt * 64;
        float4 gv, bv4;
        if (LN) {
            gv  = *reinterpret_cast<const float4*>(&lng[k0 + a_f4 * 4]);
            bv4 = *reinterpret_cast<const float4*>(&lnb[k0 + a_f4 * 4]);
        }
        #pragma unroll
        for (int it = 0; it < 8; it++) {
            int r = a_row + it * 16;
            float4 v = *reinterpret_cast<const float4*>(
                &A[(size_t)(bm + r) * EMBED + k0 + a_f4 * 4]);
            if (LN) {
                float2 st = stats[bm + r];
                v.x = fmaf((v.x - st.x) * st.y, gv.x, bv4.x);
                v.y = fmaf((v.y - st.x) * st.y, gv.y, bv4.y);
                v.z = fmaf((v.z - st.x) * st.y, gv.z, bv4.z);
                v.w = fmaf((v.w - st.x) * st.y, gv.w, bv4.w);
            }
            aS[it].x = pack_half2(v.x, v.y);
            aS[it].y = pack_half2(v.z, v.w);
        }
    };
    auto stsA = [&](int s) {
        uint32_t* As = gsh + s * STG_WORDS;
        #pragma unroll
        for (int it = 0; it < 8; it++) {
            int r = a_row + it * 16;
            As[r * A_PITCH + a_f4 * 2]     = aS[it].x;
            As[r * A_PITCH + a_f4 * 2 + 1] = aS[it].y;
        }
    };
    const int b_kr = tid >> 5;           // 0..7 (+8*it)
    const int b_n4 = (tid & 31) * 4;
    auto cpB = [&](int kt, int s) {
        const int k0w = kt * 32;
        const uint32_t b_sm = smb + (s * STG_WORDS + AS_WORDS) * 4;
        #pragma unroll
        for (int it = 0; it < 4; it++) {
            int kr = b_kr + it * 8;
            cp_async16(b_sm + (uint32_t)(kr * B_PITCH + b_n4) * 4,
                       &Bw[(size_t)(k0w + kr) * N + bn + b_n4]);
        }
        CP_COMMIT();
    };

    const int NT = 6;
    cpB(0, 0);
    ldgA(0);
    stsA(0);
    ldgA(1);
    CP_WAIT0();
    __syncthreads();

    for (int kt = 0; kt < NT; kt++) {
        const int cur = kt & 1;
        uint32_t* Asc = gsh + cur * STG_WORDS;
        uint32_t* Bsc = Asc + AS_WORDS;

        if (kt + 1 < NT) {               // stage kt+1 into cur^1
            stsA(cur ^ 1);
            cpB(kt + 1, cur ^ 1);
        }
        if (kt + 2 < NT) ldgA(kt + 2);

        #pragma unroll
        for (int ks = 0; ks < 4; ks++) {
            uint32_t af[4][4];
            #pragma unroll
            for (int mi = 0; mi < 4; mi++) {
                int row  = wm + mi * 16 + gid;
                int base = row * A_PITCH + ks * 8 + tig;
                af[mi][0] = Asc[base];
                af[mi][2] = Asc[base + 4];
                af[mi][1] = Asc[base + 8 * A_PITCH];
                af[mi][3] = Asc[base + 8 * A_PITCH + 4];
            }
            uint32_t bf[4][2];
            #pragma unroll
            for (int nj = 0; nj < 4; nj++) {
                int col = wn + nj * 8 + gid;
                bf[nj][0] = Bsc[(ks * 8 + tig)     * B_PITCH + col];
                bf[nj][1] = Bsc[(ks * 8 + tig + 4) * B_PITCH + col];
            }
            #pragma unroll
            for (int mi = 0; mi < 4; mi++)
                #pragma unroll
                for (int nj = 0; nj < 4; nj++)
                    mma_f16(acc[mi][nj], af[mi], bf[nj]);
        }
        CP_WAIT0();
        __syncthreads();
    }

    // epilogue (c-frag layout of m16n8k16 == m16n8k8)
    #pragma unroll
    for (int mi = 0; mi < 4; mi++) {
        int row = bm + wm + mi * 16 + gid;
        #pragma unroll
        for (int nj = 0; nj < 4; nj++) {
            int col = bn + wn + nj * 8 + tig * 2;
            float2 bv = *reinterpret_cast<const float2*>(&bias[col]);
            float v0 = acc[mi][nj][0] + bv.x;
            float v1 = acc[mi][nj][1] + bv.y;
            float v2 = acc[mi][nj][2] + bv.x;
            float v3 = acc[mi][nj][3] + bv.y;
            if (RELU) {
                v0 = fmaxf(v0, 0.f); v1 = fmaxf(v1, 0.f);
                v2 = fmaxf(v2, 0.f); v3 = fmaxf(v3, 0.f);
            }
            if (res) {
                float2 r0 = *reinterpret_cast<const float2*>(
                    &res[(size_t)row * N + col]);
                float2 r1 = *reinterpret_cast<const float2*>(
                    &res[(size_t)(row + 8) * N + col]);
                v0 += r0.x; v1 += r0.y; v2 += r1.x; v3 += r1.y;
            }
            *reinterpret_cast<float2*>(&C[(size_t)row * N + col]) =
                make_float2(v0, v1);
            *reinterpret_cast<float2*>(&C[(size_t)(row + 8) * N + col]) =
                make_float2(v2, v3);
        }
    }
}

// ------------------------- tensor-core flash attention (unchanged R10) ------
#define QP 68
#define SM_ATTN_BYTES ((128*QP + 2*64*QP + 2*64*QP) * 4)   // 104448

__global__ __launch_bounds__(256)
void attn_tc_kernel(const float* __restrict__ qkv, float* __restrict__ out) {
    extern __shared__ uint32_t sh[];
    uint32_t* Qs  = sh;
    uint32_t* Kb0 = sh + 128 * QP;
    uint32_t* Vb0 = sh + 128 * QP + 2 * 64 * QP;

    const int qt  = 1 - blockIdx.x;
    const int h   = blockIdx.y;
    const int b   = blockIdx.z;
    const int q0  = qt * 128;
    const int tid  = threadIdx.x;
    const int warp = tid >> 5;
    const int lane = tid & 31;
    const int gid  = lane >> 2;
    const int tig  = lane & 3;
    const int wr0  = warp * 16;
    const float qscale = rsqrtf((float)EMBED) * 1.4426950408889634f;

    #pragma unroll
    for (int it = 0; it < 8; it++) {
        int li = tid + it * 256;
        int r  = li >> 4;
        int d4 = (li & 15) * 4;
        float4 v = *reinterpret_cast<const float4*>(
            &qkv[(size_t)(b * SEQ + q0 + r) * NQKV + h * HS + d4]);
        uint4 u;
        u.x = f2tf32(v.x * qscale); u.y = f2tf32(v.y * qscale);
        u.z = f2tf32(v.z * qscale); u.w = f2tf32(v.w * qscale);
        *reinterpret_cast<uint4*>(&Qs[r * QP + d4]) = u;
    }

    const uint32_t kb_addr = smem_u32(Kb0);
    auto cpk = [&](int st, int stage) {
        const float* base = &qkv[(size_t)(b * SEQ + st * 64) * NQKV + EMBED + h * HS];
        uint32_t dst = kb_addr + (uint32_t)(stage * 64 * QP) * 4u;
        #pragma unroll
        for (int it = 0; it < 4; it++) {
            int cid = tid + it * 256;
            int r   = cid >> 4;
            int d4  = (cid & 15) * 4;
            cp_async16(dst + (uint32_t)(r * QP + d4) * 4u,
                       base + (size_t)r * NQKV + d4);
        }
        CP_COMMIT();
    };
    float4 vS[4];
    auto ldgv = [&](int st) {
        #pragma unroll
        for (int it = 0; it < 4; it++) {
            int li = tid + it * 256;
            int s  = li & 63;
            int d4 = (li >> 6) * 4;
            vS[it] = *reinterpret_cast<const float4*>(
                &qkv[(size_t)(b * SEQ + st * 64 + s) * NQKV + 2 * EMBED + h * HS + d4]);
        }
    };
    auto stsv = [&](uint32_t* Vt) {
        #pragma unroll
        for (int it = 0; it < 4; it++) {
            int li = tid + it * 256;
            int s  = li & 63;
            int d4 = (li >> 6) * 4;
            Vt[(d4 + 0) * QP + s] = f2tf32(vS[it].x);
            Vt[(d4 + 1) * QP + s] = f2tf32(vS[it].y);
            Vt[(d4 + 2) * QP + s] = f2tf32(vS[it].z);
            Vt[(d4 + 3) * QP + s] = f2tf32(vS[it].w);
        }
    };

    float oacc[8][4];
    #pragma unroll
    for (int i = 0; i < 8; i++)
        #pragma unroll
        for (int j = 0; j < 4; j++) oacc[i][j] = 0.f;
    float m0 = -1e30f, m1 = -1e30f, l0 = 0.f, l1 = 0.f;

    const int nst = q0 / 64 + 2;
    cpk(0, 0);
    ldgv(0);

    for (int st = 0; st < nst; st++) {
        const int cur = st & 1;
        uint32_t* Ks = Kb0 + cur * 64 * QP;
        uint32_t* Vt = Vb0 + cur * 64 * QP;

        __syncthreads();
        stsv(Vt);
        CP_WAIT0();
        __syncthreads();
        if (st + 1 < nst) {
            cpk(st + 1, cur ^ 1);
            ldgv(st + 1);
        }

        float sacc[8][4];
        #pragma unroll
        for (int i = 0; i < 8; i++)
            #pragma unroll
            for (int j = 0; j < 4; j++) sacc[i][j] = 0.f;

        #pragma unroll
        for (int ks = 0; ks < 8; ks++) {
            uint32_t qa[4];
            int qb = (wr0 + gid) * QP + ks * 8 + tig;
            qa[0] = Qs[qb];
            qa[1] = Qs[qb + 8 * QP];
            qa[2] = Qs[qb + 4];
            qa[3] = Qs[qb + 8 * QP + 4];
            #pragma unroll
            for (int nt = 0; nt < 8; nt++) {
                uint32_t bk[2];
                int kb = (nt * 8 + gid) * QP + ks * 8 + tig;
                bk[0] = Ks[kb];
                bk[1] = Ks[kb + 4];
                mma_tf32(sacc[nt], qa, bk);
            }
        }

        const int r0g = q0 + wr0 + gid;
        const int r1g = r0g + 8;
        if (st * 64 + 63 > r0g - gid) {
            #pragma unroll
            for (int nt = 0; nt < 8; nt++) {
                int cb = st * 64 + nt * 8 + 2 * tig;
                if (cb     > r0g) sacc[nt][0] = -1e30f;
                if (cb + 1 > r0g) sacc[nt][1] = -1e30f;
                if (cb     > r1g) sacc[nt][2] = -1e30f;
                if (cb + 1 > r1g) sacc[nt][3] = -1e30f;
            }
        }

        float mx0 = -1e30f, mx1 = -1e30f;
        #pragma unroll
        for (int nt = 0; nt < 8; nt++) {
            mx0 = fmaxf(mx0, fmaxf(sacc[nt][0], sacc[nt][1]));
            mx1 = fmaxf(mx1, fmaxf(sacc[nt][2], sacc[nt][3]));
        }
        #pragma unroll
        for (int o = 1; o <= 2; o <<= 1) {
            mx0 = fmaxf(mx0, __shfl_xor_sync(0xffffffffu, mx0, o));
            mx1 = fmaxf(mx1, __shfl_xor_sync(0xffffffffu, mx1, o));
        }
        float mn0 = fmaxf(m0, mx0), mn1 = fmaxf(m1, mx1);
        float al0 = exp2f(m0 - mn0), al1 = exp2f(m1 - mn1);
        m0 = mn0; m1 = mn1;

        float ls0 = 0.f, ls1 = 0.f;
        #pragma unroll
        for (int nt = 0; nt < 8; nt++) {
            float p0 = exp2f(sacc[nt][0] - mn0);
            float p1 = exp2f(sacc[nt][1] - mn0);
            float p2 = exp2f(sacc[nt][2] - mn1);
            float p3 = exp2f(sacc[nt][3] - mn1);
            sacc[nt][0] = p0; sacc[nt][1] = p1;
            sacc[nt][2] = p2; sacc[nt][3] = p3;
            ls0 += p0 + p1; ls1 += p2 + p3;
        }
        l0 = l0 * al0 + ls0;
        l1 = l1 * al1 + ls1;
        #pragma unroll
        for (int dn = 0; dn < 8; dn++) {
            oacc[dn][0] *= al0; oacc[dn][1] *= al0;
            oacc[dn][2] *= al1; oacc[dn][3] *= al1;
        }

        const int s0l = 4 * gid + (tig >> 1);
        const bool odd = tig & 1;
        #pragma unroll
        for (int kc = 0; kc < 8; kc++) {
            float v00 = __shfl_sync(0xffffffffu, sacc[kc][0], s0l);
            float v01 = __shfl_sync(0xffffffffu, sacc[kc][1], s0l);
            float v10 = __shfl_sync(0xffffffffu, sacc[kc][2], s0l);
            float v11 = __shfl_sync(0xffffffffu, sacc[kc][3], s0l);
            float v20 = __shfl_sync(0xffffffffu, sacc[kc][0], s0l + 2);
            float v21 = __shfl_sync(0xffffffffu, sacc[kc][1], s0l + 2);
            float v30 = __shfl_sync(0xffffffffu, sacc[kc][2], s0l + 2);
            float v31 = __shfl_sync(0xffffffffu, sacc[kc][3], s0l + 2);
            uint32_t pa[4];
            pa[0] = f2tf32(odd ? v01 : v00);
            pa[1] = f2tf32(odd ? v11 : v10);
            pa[2] = f2tf32(odd ? v21 : v20);
            pa[3] = f2tf32(odd ? v31 : v30);
            #pragma unroll
            for (int dn = 0; dn < 8; dn++) {
                uint32_t bv[2];
                int vb = (dn * 8 + gid) * QP + kc * 8 + tig;
                bv[0] = Vt[vb];
                bv[1] = Vt[vb + 4];
                mma_tf32(oacc[dn], pa, bv);
            }
        }
    }

    #pragma unroll
    for (int o = 1; o <= 2; o <<= 1) {
        l0 += __shfl_xor_sync(0xffffffffu, l0, o);
        l1 += __shfl_xor_sync(0xffffffffu, l1, o);
    }
    float inv0 = 1.f / l0, inv1 = 1.f / l1;
    const int row0 = b * SEQ + q0 + wr0 + gid;
    #pragma unroll
    for (int dn = 0; dn < 8; dn++) {
        int col = h * HS + dn * 8 + 2 * tig;
        *reinterpret_cast<float2*>(&out[(size_t)row0 * EMBED + col]) =
            make_float2(oacc[dn][0] * inv0, oacc[dn][1] * inv0);
        *reinterpret_cast<float2*>(&out[(size_t)(row0 + 8) * EMBED + col]) =
            make_float2(oacc[dn][2] * inv1, oacc[dn][3] * inv1);
    }
}

// ------------------------- launch ------------------------------------------
extern "C" void kernel_launch(void* const* d_in, const int* in_sizes, int n_in,
                              void* d_out, int out_size) {
    (void)in_sizes; (void)n_in; (void)out_size;
    const float* x     = (const float*)d_in[0];
    const float* Wq    = (const float*)d_in[1];
    const float* bq    = (const float*)d_in[2];
    const float* Wk    = (const float*)d_in[3];
    const float* bk    = (const float*)d_in[4];
    const float* Wv    = (const float*)d_in[5];
    const float* bv    = (const float*)d_in[6];
    const float* Wp    = (const float*)d_in[7];
    const float* bp    = (const float*)d_in[8];
    const float* W1    = (const float*)d_in[9];
    const float* b1    = (const float*)d_in[10];
    const float* W2    = (const float*)d_in[11];
    const float* b2    = (const float*)d_in[12];
    const float* ln1_g = (const float*)d_in[13];
    const float* ln1_b = (const float*)d_in[14];
    const float* ln2_g = (const float*)d_in[15];
    const float* ln2_b = (const float*)d_in[16];
    float* out = (float*)d_out;

    float *p_qkv, *p_attn, *p_ff, *p_bqkv;
    uint32_t *p_wqkv16, *p_wp16, *p_w116, *p_w216;
    float2* p_stats;
    cudaGetSymbolAddress((void**)&p_qkv,    g_qkv);
    cudaGetSymbolAddress((void**)&p_attn,   g_attn);
    cudaGetSymbolAddress((void**)&p_ff,     g_ff);
    cudaGetSymbolAddress((void**)&p_wqkv16, g_wqkv16);
    cudaGetSymbolAddress((void**)&p_wp16,   g_wp16);
    cudaGetSymbolAddress((void**)&p_w116,   g_w116);
    cudaGetSymbolAddress((void**)&p_w216,   g_w216);
    cudaGetSymbolAddress((void**)&p_bqkv,   g_bqkv);
    cudaGetSymbolAddress((void**)&p_stats,  g_stats);

    cudaFuncSetAttribute(attn_tc_kernel,
                         cudaFuncAttributeMaxDynamicSharedMemorySize,
                         SM_ATTN_BYTES);
    cudaFuncSetAttribute(gemm_f16<true,  false>,
                         cudaFuncAttributeMaxDynamicSharedMemorySize, SM_GEMM_BYTES);
    cudaFuncSetAttribute(gemm_f16<false, false>,
                         cudaFuncAttributeMaxDynamicSharedMemorySize, SM_GEMM_BYTES);
    cudaFuncSetAttribute(gemm_f16<true,  true>,
                         cudaFuncAttributeMaxDynamicSharedMemorySize, SM_GEMM_BYTES);

    // 1. pack weights to half2 word layout
    pack_qkv16_kernel<<<(KW * NQKV + 255) / 256, 256>>>(
        Wq, Wk, Wv, bq, bk, bv, p_wqkv16, p_bqkv);
    pack_w16_kernel<<<(KW * EMBED + 255) / 256, 256>>>(Wp, p_wp16);
    pack_w16_kernel<<<(KW * EMBED + 255) / 256, 256>>>(W1, p_w116);
    pack_w16_kernel<<<(KW * EMBED + 255) / 256, 256>>>(W2, p_w216);

    // 2. LN1 stats
    ln_stats_kernel<<<ROWS / 8, 256>>>(x, p_stats);

    // 3. QKV projection, fused LN1 (fp16 tensor cores)
    gemm_f16<true, false><<<dim3(NQKV / 128, ROWS / 128), 256, SM_GEMM_BYTES>>>(
        x, p_wqkv16, p_bqkv, nullptr, p_qkv, NQKV, p_stats, ln1_g, ln1_b);

    // 4. causal attention (tf32, unchanged)
    attn_tc_kernel<<<dim3(2, HEADS, BATCH), 256, SM_ATTN_BYTES>>>(
        p_qkv, p_attn);

    // 5. output projection + residual
    gemm_f16<false, false><<<dim3(EMBED / 128, ROWS / 128), 256, SM_GEMM_BYTES>>>(
        p_attn, p_wp16, bp, x, out, EMBED, nullptr, nullptr, nullptr);

    // 6. LN2 stats
    ln_stats_kernel<<<ROWS / 8, 256>>>(out, p_stats);

    // 7. FFN1, fused LN2 + relu
    gemm_f16<true, true><<<dim3(EMBED / 128, ROWS / 128), 256, SM_GEMM_BYTES>>>(
        out, p_w116, b1, nullptr, p_ff, EMBED, p_stats, ln2_g, ln2_b);

    // 8. FFN2 + residual
    gemm_f16<false, false><<<dim3(EMBED / 128, ROWS / 128), 256, SM_GEMM_BYTES>>>(
        p_ff, p_w216, b2, out, out, EMBED, nullptr, nullptr, nullptr);
}

// round 16
// speedup vs baseline: 1.0014x; 1.0014x over previous
#include <cuda_runtime.h>
#include <cuda_fp16.h>
#include <math.h>
#include <stdint.h>

#define EMBED 384
#define HEADS 6
#define HS    64
#define BATCH 64
#define SEQ   256
#define ROWS  (BATCH*SEQ)     // 16384
#define NQKV  (3*EMBED)       // 1152
#define KW    (EMBED/2)       // 192 k-words (half2)

// ------------------------- device scratch (no allocs allowed) ----------------
__device__ float    g_qkv   [ROWS*NQKV];
__device__ float    g_attn  [ROWS*EMBED];
__device__ float    g_ff    [ROWS*EMBED];
__device__ uint32_t g_wqkv16[KW*NQKV];    // half2 words, [k_word][n]
__device__ uint32_t g_wp16  [KW*EMBED];
__device__ uint32_t g_w116  [KW*EMBED];
__device__ uint32_t g_w216  [KW*EMBED];
__device__ float    g_bqkv  [NQKV];
__device__ float2   g_stats [ROWS];

// ------------------------- helpers ------------------------------------------
__device__ __forceinline__ uint32_t f2tf32(float x) {
    uint32_t r;
    asm("cvt.rna.tf32.f32 %0, %1;" : "=r"(r) : "f"(x));
    return r;
}

__device__ __forceinline__ uint32_t pack_half2(float a, float b) {
    __half2 h = __floats2half2_rn(a, b);
    return *reinterpret_cast<uint32_t*>(&h);
}

__device__ __forceinline__ void mma_tf32(float d[4], const uint32_t a[4],
                                         const uint32_t b[2]) {
    asm volatile(
        "mma.sync.aligned.m16n8k8.row.col.f32.tf32.tf32.f32 "
        "{%0,%1,%2,%3}, {%4,%5,%6,%7}, {%8,%9}, {%0,%1,%2,%3};\n"
        : "+f"(d[0]), "+f"(d[1]), "+f"(d[2]), "+f"(d[3])
        : "r"(a[0]), "r"(a[1]), "r"(a[2]), "r"(a[3]), "r"(b[0]), "r"(b[1]));
}

__device__ __forceinline__ void mma_f16(float d[4], const uint32_t a[4],
                                        const uint32_t b[2]) {
    asm volatile(
        "mma.sync.aligned.m16n8k16.row.col.f32.f16.f16.f32 "
        "{%0,%1,%2,%3}, {%4,%5,%6,%7}, {%8,%9}, {%0,%1,%2,%3};\n"
        : "+f"(d[0]), "+f"(d[1]), "+f"(d[2]), "+f"(d[3])
        : "r"(a[0]), "r"(a[1]), "r"(a[2]), "r"(a[3]), "r"(b[0]), "r"(b[1]));
}

__device__ __forceinline__ void cp_async16(uint32_t saddr, const void* g) {
    asm volatile("cp.async.cg.shared.global [%0], [%1], 16;"
                 :: "r"(saddr), "l"(g));
}
#define CP_COMMIT() asm volatile("cp.async.commit_group;")
#define CP_WAIT0()  asm volatile("cp.async.wait_group 0;")

__device__ __forceinline__ uint32_t smem_u32(const void* p) {
    return (uint32_t)__cvta_generic_to_shared(p);
}

// ------------------------- weight packing (half2 word layout) ---------------
__global__ void pack_qkv16_kernel(const float* __restrict__ Wq,
                                  const float* __restrict__ Wk,
                                  const float* __restrict__ Wv,
                                  const float* __restrict__ bq,
                                  const float* __restrict__ bk,
                                  const float* __restrict__ bv,
                                  uint32_t* __restrict__ Wt,
                                  float* __restrict__ bout) {
    int idx = blockIdx.x * 256 + threadIdx.x;
    if (idx < KW * NQKV) {
        int w   = idx / NQKV;        // k-word (c pair)
        int n   = idx % NQKV;
        int sel = n / EMBED;
        int hd  = n % EMBED;
        int h   = hd / HS;
        int d   = hd % HS;
        const float* W = (sel == 0) ? Wq : (sel == 1) ? Wk : Wv;
        float v0 = W[((size_t)h * EMBED + 2 * w)     * HS + d];
        float v1 = W[((size_t)h * EMBED + 2 * w + 1) * HS + d];
        Wt[idx] = pack_half2(v0, v1);
    }
    if (idx < NQKV) {
        int sel = idx / EMBED;
        int hd  = idx % EMBED;
        const float* bb = (sel == 0) ? bq : (sel == 1) ? bk : bv;
        bout[idx] = bb[hd];
    }
}

__global__ void pack_w16_kernel(const float* __restrict__ W,
                                uint32_t* __restrict__ Wt) {
    int idx = blockIdx.x * 256 + threadIdx.x;
    if (idx < KW * EMBED) {
        int w = idx / EMBED;
        int n = idx % EMBED;
        Wt[idx] = pack_half2(W[(size_t)(2 * w) * EMBED + n],
                             W[(size_t)(2 * w + 1) * EMBED + n]);
    }
}

// ------------------------- LN stats ------------------------------------------
__global__ __launch_bounds__(256)
void ln_stats_kernel(const float* __restrict__ x, float2* __restrict__ st) {
    int row  = blockIdx.x * 8 + (threadIdx.x >> 5);
    int lane = threadIdx.x & 31;
    const float4* xr = reinterpret_cast<const float4*>(x + (size_t)row * EMBED);
    float s = 0.f, s2 = 0.f;
    #pragma unroll
    for (int i = 0; i < 3; i++) {
        float4 v = xr[lane + 32 * i];
        s  += v.x + v.y + v.z + v.w;
        s2 += v.x * v.x + v.y * v.y + v.z * v.z + v.w * v.w;
    }
    #pragma unroll
    for (int o = 16; o; o >>= 1) {
        s  += __shfl_xor_sync(0xffffffffu, s,  o);
        s2 += __shfl_xor_sync(0xffffffffu, s2, o);
    }
    if (lane == 0) {
        float mu  = s * (1.0f / EMBED);
        float var = s2 * (1.0f / EMBED) - mu * mu;
        st[row] = make_float2(mu, rsqrtf(var + 1e-5f));
    }
}

// ------------------------- FP16 tensor-core GEMM ----------------------------
// C[M,N] = A'[M,384] @ B[384,N] (+bias, opt relu, opt residual)
// A' = LN ? layernorm(A) : A (f32 in gmem, converted RN to half on STS).
// B pre-packed half2 words [k_word][n].  CTA 128x128, k-tile 64 (=32 words),
// 6 k-tiles, double-buffered, one sync per tile. mma m16n8k16 f16, f32 accum.
#define A_PITCH 36     // words; frag addr mod 32 = 4*gid + tig -> conflict-free
#define B_PITCH 136    // words; 136 mod 32 = 8 -> 8*tig + gid -> conflict-free
#define AS_WORDS (128 * A_PITCH)                 // 4608
#define BS_WORDS (32 * B_PITCH)                  // 4352
#define STG_WORDS (AS_WORDS + BS_WORDS)          // 8960
#define SM_GEMM_BYTES (2 * STG_WORDS * 4)        // 71680

template<bool LN, bool RELU>
__global__ __launch_bounds__(256)
void gemm_f16(const float* __restrict__ A, const uint32_t* __restrict__ Bw,
              const float* __restrict__ bias, const float* __restrict__ res,
              float* __restrict__ C, int N,
              const float2* __restrict__ stats,
              const float* __restrict__ lng, const float* __restrict__ lnb) {
    extern __shared__ uint32_t gsh[];
    const uint32_t smb = smem_u32(gsh);

    const int tid  = threadIdx.x;
    const int bm   = blockIdx.y * 128;
    const int bn   = blockIdx.x * 128;
    const int warp = tid >> 5;
    const int lane = tid & 31;
    const int wm   = (warp >> 2) * 64;
    const int wn   = (warp & 3) * 32;
    const int gid  = lane >> 2;
    const int tig  = lane & 3;

    float acc[4][4][4];
    #pragma unroll
    for (int i = 0; i < 4; i++)
        #pragma unroll
        for (int j = 0; j < 4; j++)
            #pragma unroll
            for (int r = 0; r < 4; r++) acc[i][j][r] = 0.f;

    // A staging: 8 chunks of float4 -> 2 half2 words each
    uint2 aS[8];
    const int a_row = tid >> 4;          // 0..15 (+16*it)
    const int a_f4  = tid & 15;          // float4 index within 64-float row

    auto ldgA = [&](int kt) {
        const int k0 = kt * 64;
        float4 gv, bv4;
        if (LN) {
            gv  = *reinterpret_cast<const float4*>(&lng[k0 + a_f4 * 4]);
            bv4 = *reinterpret_cast<const float4*>(&lnb[k0 + a_f4 * 4]);
        }
        #pragma unroll
        for (int it = 0; it < 8; it++) {
            int r = a_row + it * 16;
            float4 v = *reinterpret_cast<const float4*>(
                &A[(size_t)(bm + r) * EMBED + k0 + a_f4 * 4]);
            if (LN) {
                float2 st = stats[bm + r];
                v.x = fmaf((v.x - st.x) * st.y, gv.x, bv4.x);
                v.y = fmaf((v.y - st.x) * st.y, gv.y, bv4.y);
                v.z = fmaf((v.z - st.x) * st.y, gv.z, bv4.z);
                v.w = fmaf((v.w - st.x) * st.y, gv.w, bv4.w);
            }
            aS[it].x = pack_half2(v.x, v.y);
            aS[it].y = pack_half2(v.z, v.w);
        }
    };
    auto stsA = [&](int s) {
        uint32_t* As = gsh + s * STG_WORDS;
        #pragma unroll
        for (int it = 0; it < 8; it++) {
            int r = a_row + it * 16;
            As[r * A_PITCH + a_f4 * 2]     = aS[it].x;
            As[r * A_PITCH + a_f4 * 2 + 1] = aS[it].y;
        }
    };
    const int b_kr = tid >> 5;           // 0..7 (+8*it)
    const int b_n4 = (tid & 31) * 4;
    auto cpB = [&](int kt, int s) {
        const int k0w = kt * 32;
        const uint32_t b_sm = smb + (s * STG_WORDS + AS_WORDS) * 4;
        #pragma unroll
        for (int it = 0; it < 4; it++) {
            int kr = b_kr + it * 8;
            cp_async16(b_sm + (uint32_t)(kr * B_PITCH + b_n4) * 4,
                       &Bw[(size_t)(k0w + kr) * N + bn + b_n4]);
        }
        CP_COMMIT();
    };

    const int NT = 6;
    cpB(0, 0);
    ldgA(0);
    stsA(0);
    ldgA(1);
    CP_WAIT0();
    __syncthreads();

    for (int kt = 0; kt < NT; kt++) {
        const int cur = kt & 1;
        uint32_t* Asc = gsh + cur * STG_WORDS;
        uint32_t* Bsc = Asc + AS_WORDS;

        if (kt + 1 < NT) {               // stage kt+1 into cur^1
            stsA(cur ^ 1);
            cpB(kt + 1, cur ^ 1);
        }
        if (kt + 2 < NT) ldgA(kt + 2);

        #pragma unroll
        for (int ks = 0; ks < 4; ks++) {
            uint32_t af[4][4];
            #pragma unroll
            for (int mi = 0; mi < 4; mi++) {
                int row  = wm + mi * 16 + gid;
                int base = row * A_PITCH + ks * 8 + tig;
                af[mi][0] = Asc[base];
                af[mi][2] = Asc[base + 4];
                af[mi][1] = Asc[base + 8 * A_PITCH];
                af[mi][3] = Asc[base + 8 * A_PITCH + 4];
            }
            uint32_t bf[4][2];
            #pragma unroll
            for (int nj = 0; nj < 4; nj++) {
                int col = wn + nj * 8 + gid;
                bf[nj][0] = Bsc[(ks * 8 + tig)     * B_PITCH + col];
                bf[nj][1] = Bsc[(ks * 8 + tig + 4) * B_PITCH + col];
            }
            #pragma unroll
            for (int mi = 0; mi < 4; mi++)
                #pragma unroll
                for (int nj = 0; nj < 4; nj++)
                    mma_f16(acc[mi][nj], af[mi], bf[nj]);
        }
        CP_WAIT0();
        __syncthreads();
    }

    // epilogue (c-frag layout of m16n8k16 == m16n8k8)
    #pragma unroll
    for (int mi = 0; mi < 4; mi++) {
        int row = bm + wm + mi * 16 + gid;
        #pragma unroll
        for (int nj = 0; nj < 4; nj++) {
            int col = bn + wn + nj * 8 + tig * 2;
            float2 bv = *reinterpret_cast<const float2*>(&bias[col]);
            float v0 = acc[mi][nj][0] + bv.x;
            float v1 = acc[mi][nj][1] + bv.y;
            float v2 = acc[mi][nj][2] + bv.x;
            float v3 = acc[mi][nj][3] + bv.y;
            if (RELU) {
                v0 = fmaxf(v0, 0.f); v1 = fmaxf(v1, 0.f);
                v2 = fmaxf(v2, 0.f); v3 = fmaxf(v3, 0.f);
            }
            if (res) {
                float2 r0 = *reinterpret_cast<const float2*>(
                    &res[(size_t)row * N + col]);
                float2 r1 = *reinterpret_cast<const float2*>(
                    &res[(size_t)(row + 8) * N + col]);
                v0 += r0.x; v1 += r0.y; v2 += r1.x; v3 += r1.y;
            }
            *reinterpret_cast<float2*>(&C[(size_t)row * N + col]) =
                make_float2(v0, v1);
            *reinterpret_cast<float2*>(&C[(size_t)(row + 8) * N + col]) =
                make_float2(v2, v3);
        }
    }
}

// ------------------------- tensor-core flash attention (unchanged R10) ------
#define QP 68
#define SM_ATTN_BYTES ((128*QP + 2*64*QP + 2*64*QP) * 4)   // 104448

__global__ __launch_bounds__(256)
void attn_tc_kernel(const float* __restrict__ qkv, float* __restrict__ out) {
    extern __shared__ uint32_t sh[];
    uint32_t* Qs  = sh;
    uint32_t* Kb0 = sh + 128 * QP;
    uint32_t* Vb0 = sh + 128 * QP + 2 * 64 * QP;

    const int qt  = 1 - blockIdx.x;
    const int h   = blockIdx.y;
    const int b   = blockIdx.z;
    const int q0  = qt * 128;
    const int tid  = threadIdx.x;
    const int warp = tid >> 5;
    const int lane = tid & 31;
    const int gid  = lane >> 2;
    const int tig  = lane & 3;
    const int wr0  = warp * 16;
    const float qscale = rsqrtf((float)EMBED) * 1.4426950408889634f;

    #pragma unroll
    for (int it = 0; it < 8; it++) {
        int li = tid + it * 256;
        int r  = li >> 4;
        int d4 = (li & 15) * 4;
        float4 v = *reinterpret_cast<const float4*>(
            &qkv[(size_t)(b * SEQ + q0 + r) * NQKV + h * HS + d4]);
        uint4 u;
        u.x = f2tf32(v.x * qscale); u.y = f2tf32(v.y * qscale);
        u.z = f2tf32(v.z * qscale); u.w = f2tf32(v.w * qscale);
        *reinterpret_cast<uint4*>(&Qs[r * QP + d4]) = u;
    }

    const uint32_t kb_addr = smem_u32(Kb0);
    auto cpk = [&](int st, int stage) {
        const float* base = &qkv[(size_t)(b * SEQ + st * 64) * NQKV + EMBED + h * HS];
        uint32_t dst = kb_addr + (uint32_t)(stage * 64 * QP) * 4u;
        #pragma unroll
        for (int it = 0; it < 4; it++) {
            int cid = tid + it * 256;
            int r   = cid >> 4;
            int d4  = (cid & 15) * 4;
            cp_async16(dst + (uint32_t)(r * QP + d4) * 4u,
                       base + (size_t)r * NQKV + d4);
        }
        CP_COMMIT();
    };
    float4 vS[4];
    auto ldgv = [&](int st) {
        #pragma unroll
        for (int it = 0; it < 4; it++) {
            int li = tid + it * 256;
            int s  = li & 63;
            int d4 = (li >> 6) * 4;
            vS[it] = *reinterpret_cast<const float4*>(
                &qkv[(size_t)(b * SEQ + st * 64 + s) * NQKV + 2 * EMBED + h * HS + d4]);
        }
    };
    auto stsv = [&](uint32_t* Vt) {
        #pragma unroll
        for (int it = 0; it < 4; it++) {
            int li = tid + it * 256;
            int s  = li & 63;
            int d4 = (li >> 6) * 4;
            Vt[(d4 + 0) * QP + s] = f2tf32(vS[it].x);
            Vt[(d4 + 1) * QP + s] = f2tf32(vS[it].y);
            Vt[(d4 + 2) * QP + s] = f2tf32(vS[it].z);
            Vt[(d4 + 3) * QP + s] = f2tf32(vS[it].w);
        }
    };

    float oacc[8][4];
    #pragma unroll
    for (int i = 0; i < 8; i++)
        #pragma unroll
        for (int j = 0; j < 4; j++) oacc[i][j] = 0.f;
    float m0 = -1e30f, m1 = -1e30f, l0 = 0.f, l1 = 0.f;

    const int nst = q0 / 64 + 2;
    cpk(0, 0);
    ldgv(0);

    for (int st = 0; st < nst; st++) {
        const int cur = st & 1;
        uint32_t* Ks = Kb0 + cur * 64 * QP;
        uint32_t* Vt = Vb0 + cur * 64 * QP;

        __syncthreads();
        stsv(Vt);
        CP_WAIT0();
        __syncthreads();
        if (st + 1 < nst) {
            cpk(st + 1, cur ^ 1);
            ldgv(st + 1);
        }

        float sacc[8][4];
        #pragma unroll
        for (int i = 0; i < 8; i++)
            #pragma unroll
            for (int j = 0; j < 4; j++) sacc[i][j] = 0.f;

        #pragma unroll
        for (int ks = 0; ks < 8; ks++) {
            uint32_t qa[4];
            int qb = (wr0 + gid) * QP + ks * 8 + tig;
            qa[0] = Qs[qb];
            qa[1] = Qs[qb + 8 * QP];
            qa[2] = Qs[qb + 4];
            qa[3] = Qs[qb + 8 * QP + 4];
            #pragma unroll
            for (int nt = 0; nt < 8; nt++) {
                uint32_t bk[2];
                int kb = (nt * 8 + gid) * QP + ks * 8 + tig;
                bk[0] = Ks[kb];
                bk[1] = Ks[kb + 4];
                mma_tf32(sacc[nt], qa, bk);
            }
        }

        const int r0g = q0 + wr0 + gid;
        const int r1g = r0g + 8;
        if (st * 64 + 63 > r0g - gid) {
            #pragma unroll
            for (int nt = 0; nt < 8; nt++) {
                int cb = st * 64 + nt * 8 + 2 * tig;
                if (cb     > r0g) sacc[nt][0] = -1e30f;
                if (cb + 1 > r0g) sacc[nt][1] = -1e30f;
                if (cb     > r1g) sacc[nt][2] = -1e30f;
                if (cb + 1 > r1g) sacc[nt][3] = -1e30f;
            }
        }

        float mx0 = -1e30f, mx1 = -1e30f;
        #pragma unroll
        for (int nt = 0; nt < 8; nt++) {
            mx0 = fmaxf(mx0, fmaxf(sacc[nt][0], sacc[nt][1]));
            mx1 = fmaxf(mx1, fmaxf(sacc[nt][2], sacc[nt][3]));
        }
        #pragma unroll
        for (int o = 1; o <= 2; o <<= 1) {
            mx0 = fmaxf(mx0, __shfl_xor_sync(0xffffffffu, mx0, o));
            mx1 = fmaxf(mx1, __shfl_xor_sync(0xffffffffu, mx1, o));
        }
        float mn0 = fmaxf(m0, mx0), mn1 = fmaxf(m1, mx1);
        float al0 = exp2f(m0 - mn0), al1 = exp2f(m1 - mn1);
        m0 = mn0; m1 = mn1;

        float ls0 = 0.f, ls1 = 0.f;
        #pragma unroll
        for (int nt = 0; nt < 8; nt++) {
            float p0 = exp2f(sacc[nt][0] - mn0);
            float p1 = exp2f(sacc[nt][1] - mn0);
            float p2 = exp2f(sacc[nt][2] - mn1);
            float p3 = exp2f(sacc[nt][3] - mn1);
            sacc[nt][0] = p0; sacc[nt][1] = p1;
            sacc[nt][2] = p2; sacc[nt][3] = p3;
            ls0 += p0 + p1; ls1 += p2 + p3;
        }
        l0 = l0 * al0 + ls0;
        l1 = l1 * al1 + ls1;
        #pragma unroll
        for (int dn = 0; dn < 8; dn++) {
            oacc[dn][0] *= al0; oacc[dn][1] *= al0;
            oacc[dn][2] *= al1; oacc[dn][3] *= al1;
        }

        const int s0l = 4 * gid + (tig >> 1);
        const bool odd = tig & 1;
        #pragma unroll
        for (int kc = 0; kc < 8; kc++) {
            float v00 = __shfl_sync(0xffffffffu, sacc[kc][0], s0l);
            float v01 = __shfl_sync(0xffffffffu, sacc[kc][1], s0l);
            float v10 = __shfl_sync(0xffffffffu, sacc[kc][2], s0l);
            float v11 = __shfl_sync(0xffffffffu, sacc[kc][3], s0l);
            float v20 = __shfl_sync(0xffffffffu, sacc[kc][0], s0l + 2);
            float v21 = __shfl_sync(0xffffffffu, sacc[kc][1], s0l + 2);
            float v30 = __shfl_sync(0xffffffffu, sacc[kc][2], s0l + 2);
            float v31 = __shfl_sync(0xffffffffu, sacc[kc][3], s0l + 2);
            uint32_t pa[4];
            pa[0] = f2tf32(odd ? v01 : v00);
            pa[1] = f2tf32(odd ? v11 : v10);
            pa[2] = f2tf32(odd ? v21 : v20);
            pa[3] = f2tf32(odd ? v31 : v30);
            #pragma unroll
            for (int dn = 0; dn < 8; dn++) {
                uint32_t bv[2];
                int vb = (dn * 8 + gid) * QP + kc * 8 + tig;
                bv[0] = Vt[vb];
                bv[1] = Vt[vb + 4];
                mma_tf32(oacc[dn], pa, bv);
            }
        }
    }

    #pragma unroll
    for (int o = 1; o <= 2; o <<= 1) {
        l0 += __shfl_xor_sync(0xffffffffu, l0, o);
        l1 += __shfl_xor_sync(0xffffffffu, l1, o);
    }
    float inv0 = 1.f / l0, inv1 = 1.f / l1;
    const int row0 = b * SEQ + q0 + wr0 + gid;
    #pragma unroll
    for (int dn = 0; dn < 8; dn++) {
        int col = h * HS + dn * 8 + 2 * tig;
        *reinterpret_cast<float2*>(&out[(size_t)row0 * EMBED + col]) =
            make_float2(oacc[dn][0] * inv0, oacc[dn][1] * inv0);
        *reinterpret_cast<float2*>(&out[(size_t)(row0 + 8) * EMBED + col]) =
            make_float2(oacc[dn][2] * inv1, oacc[dn][3] * inv1);
    }
}

// ------------------------- launch ------------------------------------------
extern "C" void kernel_launch(void* const* d_in, const int* in_sizes, int n_in,
                              void* d_out, int out_size) {
    (void)in_sizes; (void)n_in; (void)out_size;
    const float* x     = (const float*)d_in[0];
    const float* Wq    = (const float*)d_in[1];
    const float* bq    = (const float*)d_in[2];
    const float* Wk    = (const float*)d_in[3];
    const float* bk    = (const float*)d_in[4];
    const float* Wv    = (const float*)d_in[5];
    const float* bv    = (const float*)d_in[6];
    const float* Wp    = (const float*)d_in[7];
    const float* bp    = (const float*)d_in[8];
    const float* W1    = (const float*)d_in[9];
    const float* b1    = (const float*)d_in[10];
    const float* W2    = (const float*)d_in[11];
    const float* b2    = (const float*)d_in[12];
    const float* ln1_g = (const float*)d_in[13];
    const float* ln1_b = (const float*)d_in[14];
    const float* ln2_g = (const float*)d_in[15];
    const float* ln2_b = (const float*)d_in[16];
    float* out = (float*)d_out;

    float *p_qkv, *p_attn, *p_ff, *p_bqkv;
    uint32_t *p_wqkv16, *p_wp16, *p_w116, *p_w216;
    float2* p_stats;
    cudaGetSymbolAddress((void**)&p_qkv,    g_qkv);
    cudaGetSymbolAddress((void**)&p_attn,   g_attn);
    cudaGetSymbolAddress((void**)&p_ff,     g_ff);
    cudaGetSymbolAddress((void**)&p_wqkv16, g_wqkv16);
    cudaGetSymbolAddress((void**)&p_wp16,   g_wp16);
    cudaGetSymbolAddress((void**)&p_w116,   g_w116);
    cudaGetSymbolAddress((void**)&p_w216,   g_w216);
    cudaGetSymbolAddress((void**)&p_bqkv,   g_bqkv);
    cudaGetSymbolAddress((void**)&p_stats,  g_stats);

    cudaFuncSetAttribute(attn_tc_kernel,
                         cudaFuncAttributeMaxDynamicSharedMemorySize,
                         SM_ATTN_BYTES);
    cudaFuncSetAttribute(gemm_f16<true,  false>,
                         cudaFuncAttributeMaxDynamicSharedMemorySize, SM_GEMM_BYTES);
    cudaFuncSetAttribute(gemm_f16<false, false>,
                         cudaFuncAttributeMaxDynamicSharedMemorySize, SM_GEMM_BYTES);
    cudaFuncSetAttribute(gemm_f16<true,  true>,
                         cudaFuncAttributeMaxDynamicSharedMemorySize, SM_GEMM_BYTES);

    // 1. pack weights to half2 word layout
    pack_qkv16_kernel<<<(KW * NQKV + 255) / 256, 256>>>(
        Wq, Wk, Wv, bq, bk, bv, p_wqkv16, p_bqkv);
    pack_w16_kernel<<<(KW * EMBED + 255) / 256, 256>>>(Wp, p_wp16);
    pack_w16_kernel<<<(KW * EMBED + 255) / 256, 256>>>(W1, p_w116);
    pack_w16_kernel<<<(KW * EMBED + 255) / 256, 256>>>(W2, p_w216);

    // 2. LN1 stats
    ln_stats_kernel<<<ROWS / 8, 256>>>(x, p_stats);

    // 3. QKV projection, fused LN1 (fp16 tensor cores)
    gemm_f16<true, false><<<dim3(NQKV / 128, ROWS / 128), 256, SM_GEMM_BYTES>>>(
        x, p_wqkv16, p_bqkv, nullptr, p_qkv, NQKV, p_stats, ln1_g, ln1_b);

    // 4. causal attention (tf32, unchanged)
    attn_tc_kernel<<<dim3(2, HEADS, BATCH), 256, SM_ATTN_BYTES>>>(
        p_qkv, p_attn);

    // 5. output projection + residual
    gemm_f16<false, false><<<dim3(EMBED / 128, ROWS / 128), 256, SM_GEMM_BYTES>>>(
        p_attn, p_wp16, bp, x, out, EMBED, nullptr, nullptr, nullptr);

    // 6. LN2 stats
    ln_stats_kernel<<<ROWS / 8, 256>>>(out, p_stats);

    // 7. FFN1, fused LN2 + relu
    gemm_f16<true, true><<<dim3(EMBED / 128, ROWS / 128), 256, SM_GEMM_BYTES>>>(
        out, p_w116, b1, nullptr, p_ff, EMBED, p_stats, ln2_g, ln2_b);

    // 8. FFN2 + residual
    gemm_f16<false, false><<<dim3(EMBED / 128, ROWS / 128), 256, SM_GEMM_BYTES>>>(
        p_ff, p_w216, b2, out, out, EMBED, nullptr, nullptr, nullptr);
}